// round 5
// baseline (speedup 1.0000x reference)
#include <cuda_runtime.h>

#define L 2048
#define B 32
#define H 1024
#define H4 (H / 4)
#define GCH 32            // g-chunks for K1 partials
#define GSZ (H / GCH)     // 32 g per chunk
#define LTILES 64
#define LPT (L / LTILES)  // 32 l-positions per K2 block

// Scratch (allocation-free rule: __device__ globals)
__device__ float g_vpart[GCH][B][H];   // 4 MB partial v (L2-resident)
__device__ float g_v[B][H];            // 128 KB reduced v
__device__ float g_energy[B][L];       // 256 KB energies

// ---------------------------------------------------------------------------
// K1: vpart[gc][b][h] = sum_{g in chunk} hidden[b,g] * W[g,h]
// grid (H4/32=8, GCH=32) = 256 blocks; block 256 = 32 h-quads x 8 b-quads.
// Thread: 32 independent LDG.128 of W, 4 b-accumulators, 512 FMA.
// ---------------------------------------------------------------------------
__global__ void k1_proj(const float* __restrict__ hidden,
                        const float* __restrict__ W) {
    const int tid = threadIdx.x;
    const int hq  = tid & 31;                    // 0..31 h-quad
    const int bq  = tid >> 5;                    // 0..7 -> b in [bq*4, bq*4+4)
    const int hq_glob = blockIdx.x * 32 + hq;    // float4 col index
    const int g0  = blockIdx.y * GSZ;

    __shared__ float hsh[B][GSZ];                // 4 KB hidden chunk
    {
        // B*GSZ/4 = 256 float4 loads, one per thread
        const int bb = tid >> 3, g4 = tid & 7;
        ((float4*)hsh[bb])[g4] =
            ((const float4*)hidden)[(size_t)bb * H4 + (g0 >> 2) + g4];
    }
    __syncthreads();

    float4 acc[4];
    #pragma unroll
    for (int j = 0; j < 4; j++) acc[j] = make_float4(0.f, 0.f, 0.f, 0.f);

    const float4* __restrict__ W4 = (const float4*)W;
    #pragma unroll 8
    for (int g = 0; g < GSZ; g++) {
        const float4 w = W4[(size_t)(g0 + g) * H4 + hq_glob];
        #pragma unroll
        for (int j = 0; j < 4; j++) {
            const float hv = hsh[bq * 4 + j][g];   // smem broadcast
            acc[j].x += w.x * hv; acc[j].y += w.y * hv;
            acc[j].z += w.z * hv; acc[j].w += w.w * hv;
        }
    }

    #pragma unroll
    for (int j = 0; j < 4; j++)
        *(float4*)&g_vpart[blockIdx.y][bq * 4 + j][hq_glob * 4] = acc[j];
}

// ---------------------------------------------------------------------------
// K1b: g_v[b][h] = sum_p g_vpart[p][b][h].  8192 float4 outputs, 1/thread.
// grid 32, block 256. 32 L2 loads per thread, unroll-batched.
// ---------------------------------------------------------------------------
__global__ void k1b_reduce() {
    const int idx = blockIdx.x * 256 + threadIdx.x;   // float4 index 0..8191
    const int b  = idx / H4;
    const int h4 = idx % H4;
    float4 s = make_float4(0.f, 0.f, 0.f, 0.f);
    #pragma unroll 8
    for (int p = 0; p < GCH; p++) {
        const float4 v = *(const float4*)&g_vpart[p][b][h4 * 4];
        s.x += v.x; s.y += v.y; s.z += v.z; s.w += v.w;
    }
    *(float4*)&g_v[b][h4 * 4] = s;
}

// ---------------------------------------------------------------------------
// K2: energies[b][l] = dot(enc[l,b,:], v[b,:])
// grid (LTILES=64, B) = 2048 blocks, block 256 (8 warps x 4 l's each).
// At DRAM roofline (~8 TB/s) — do not disturb.
// ---------------------------------------------------------------------------
__global__ void k2_energy(const float* __restrict__ enc) {
    const int b  = blockIdx.y;
    const int l0 = blockIdx.x * LPT;
    const int tid = threadIdx.x;

    __shared__ float4 vsh[H4];   // 4 KB
    vsh[tid] = *(const float4*)&g_v[b][tid * 4];
    __syncthreads();

    const int warp = tid >> 5, lane = tid & 31;
    const float4* __restrict__ enc4 = (const float4*)enc;

    const int la = l0 + warp * 4;
    size_t base[4];
    #pragma unroll
    for (int j = 0; j < 4; j++)
        base[j] = ((size_t)(la + j) * B + b) * H4;

    float a0 = 0.f, a1 = 0.f, a2 = 0.f, a3 = 0.f;
    #pragma unroll
    for (int k = 0; k < 8; k++) {
        const float4 v  = vsh[k * 32 + lane];
        const float4 e0 = __ldcs(&enc4[base[0] + k * 32 + lane]);
        const float4 e1 = __ldcs(&enc4[base[1] + k * 32 + lane]);
        const float4 e2 = __ldcs(&enc4[base[2] + k * 32 + lane]);
        const float4 e3 = __ldcs(&enc4[base[3] + k * 32 + lane]);
        a0 += e0.x * v.x + e0.y * v.y + e0.z * v.z + e0.w * v.w;
        a1 += e1.x * v.x + e1.y * v.y + e1.z * v.z + e1.w * v.w;
        a2 += e2.x * v.x + e2.y * v.y + e2.z * v.z + e2.w * v.w;
        a3 += e3.x * v.x + e3.y * v.y + e3.z * v.z + e3.w * v.w;
    }
    #pragma unroll
    for (int s = 16; s; s >>= 1) {
        a0 += __shfl_down_sync(0xffffffffu, a0, s);
        a1 += __shfl_down_sync(0xffffffffu, a1, s);
        a2 += __shfl_down_sync(0xffffffffu, a2, s);
        a3 += __shfl_down_sync(0xffffffffu, a3, s);
    }
    if (lane == 0) {
        g_energy[b][la + 0] = a0;
        g_energy[b][la + 1] = a1;
        g_energy[b][la + 2] = a2;
        g_energy[b][la + 3] = a3;
    }
}

// ---------------------------------------------------------------------------
// K3: masked softmax per batch row. grid B, block 512, float4 per thread.
// ---------------------------------------------------------------------------
__global__ void k3_softmax(const int* __restrict__ lengths,
                           float* __restrict__ out) {
    const int b   = blockIdx.x;
    const int len = lengths[b];
    const int tid = threadIdx.x;
    const int l0  = tid * 4;

    const float4 e = ((const float4*)&g_energy[b][0])[tid];

    float mx = -3.4e38f;
    if (l0 + 0 < len) mx = e.x;
    if (l0 + 1 < len) mx = fmaxf(mx, e.y);
    if (l0 + 2 < len) mx = fmaxf(mx, e.z);
    if (l0 + 3 < len) mx = fmaxf(mx, e.w);

    __shared__ float red_m[16], red_s[16];
    #pragma unroll
    for (int s = 16; s; s >>= 1)
        mx = fmaxf(mx, __shfl_xor_sync(0xffffffffu, mx, s));
    if ((tid & 31) == 0) red_m[tid >> 5] = mx;
    __syncthreads();
    if (tid < 32) {
        float m = (tid < 16) ? red_m[tid] : -3.4e38f;
        #pragma unroll
        for (int s = 8; s; s >>= 1)
            m = fmaxf(m, __shfl_xor_sync(0xffffffffu, m, s));
        if (tid == 0) red_m[0] = m;
    }
    __syncthreads();
    mx = red_m[0];

    float4 x;
    x.x = (l0 + 0 < len) ? expf(e.x - mx) : 0.f;
    x.y = (l0 + 1 < len) ? expf(e.y - mx) : 0.f;
    x.z = (l0 + 2 < len) ? expf(e.z - mx) : 0.f;
    x.w = (l0 + 3 < len) ? expf(e.w - mx) : 0.f;

    float sum = x.x + x.y + x.z + x.w;
    #pragma unroll
    for (int s = 16; s; s >>= 1)
        sum += __shfl_xor_sync(0xffffffffu, sum, s);
    if ((tid & 31) == 0) red_s[tid >> 5] = sum;
    __syncthreads();
    if (tid < 32) {
        float m = (tid < 16) ? red_s[tid] : 0.f;
        #pragma unroll
        for (int s = 8; s; s >>= 1)
            m += __shfl_xor_sync(0xffffffffu, m, s);
        if (tid == 0) red_s[0] = m;
    }
    __syncthreads();
    const float inv = 1.f / red_s[0];

    x.x *= inv; x.y *= inv; x.z *= inv; x.w *= inv;
    ((float4*)(out + (size_t)b * L))[tid] = x;
}

// ---------------------------------------------------------------------------
extern "C" void kernel_launch(void* const* d_in, const int* in_sizes, int n_in,
                              void* d_out, int out_size) {
    const float* hidden  = (const float*)d_in[0];   // [1,B,H]
    const float* enc     = (const float*)d_in[1];   // [L,B,H]
    const float* W       = (const float*)d_in[2];   // [H,H]
    // d_in[3] = bias — provably cancels in softmax, unused
    const int*   lengths = (const int*)d_in[4];     // [B]
    float* out = (float*)d_out;                     // [B,1,L]

    dim3 g1(H4 / 32, GCH);
    k1_proj<<<g1, 256>>>(hidden, W);

    k1b_reduce<<<32, 256>>>();

    dim3 g2(LTILES, B);
    k2_energy<<<g2, 256>>>(enc);

    k3_softmax<<<B, 512>>>(lengths, out);
}